// round 1
// baseline (speedup 1.0000x reference)
#include <cuda_runtime.h>

// 2x upsample stage: zero-stuff (offset OFF) + separable circular 23-tap conv,
// exploited as halfband polyphase: parity==OFF positions are copies, the other
// parity is a 12-tap interpolation with weights kernel[0,2,...,22].
//
// Stage 1: 256 -> 512 (OFF=1), Stage 2: 512 -> 1024 (OFF=0).

#define TT   32          // tile edge in input domain
#define INW  44          // TT + 12 halo
#define SPAN 45          // padded smem stride for input tile
#define HIW  33          // padded smem stride for H-interp tile

// Intermediate 32 channels x 512 x 512 fp32 (33.5 MB) — static device scratch.
__device__ float g_mid[32u * 512u * 512u];

template<int OFF>
__global__ __launch_bounds__(256) void up2x_kernel(
    const float* __restrict__ in, const float* __restrict__ kern,
    float* __restrict__ out, int N)
{
    __shared__ float s_in[INW * SPAN];   // input tile + halo
    __shared__ float s_hi[INW * HIW];    // H-interp columns (one per input col in tile)

    const int ch = blockIdx.z;
    const int R0 = blockIdx.y * TT;
    const int C0 = blockIdx.x * TT;
    const float* inc  = in  + (size_t)ch * N * N;
    float*       outc = out + (size_t)ch * 4u * (size_t)N * N;

    // 12 interpolation weights: kernel at even indices (odd offsets from center)
    float w[12];
#pragma unroll
    for (int u = 0; u < 12; u++) w[u] = kern[2 * u];

    const int tid = threadIdx.y * 16 + threadIdx.x;

    // --- load input tile + 6-halo with circular wrap ---
    for (int idx = tid; idx < INW * INW; idx += 256) {
        int i = idx / INW, j = idx - i * INW;
        int gr = R0 - 6 + i; if (gr < 0) gr += N; else if (gr >= N) gr -= N;
        int gc = C0 - 6 + j; if (gc < 0) gc += N; else if (gc >= N) gc -= N;
        s_in[i * SPAN + j] = inc[(size_t)gr * N + gc];
    }
    __syncthreads();

    const int SH = OFF ? 0 : 1;   // interp window shift: off=1 -> m+u-6, off=0 -> m+u-5

    // --- horizontal interpolation for every loaded row ---
    for (int idx = tid; idx < INW * TT; idx += 256) {
        int i = idx >> 5, m = idx & 31;            // TT == 32
        const float* row = &s_in[i * SPAN + m + SH];
        float acc = 0.f;
#pragma unroll
        for (int u = 0; u < 12; u++) acc += w[u] * row[u];
        s_hi[i * HIW + m] = acc;
    }
    __syncthreads();

    // --- emit 64x64 output tile; each thread 4 rows x 4 consecutive cols (float4 store) ---
    const int tx = threadIdx.x, ty = threadIdx.y;
    const size_t W2 = 2 * (size_t)N;
#pragma unroll
    for (int k = 0; k < 4; k++) {
        int qr = 4 * ty + k;
        int rr = qr >> 1;
        bool rcopy = ((qr & 1) == OFF);
        float res[4];
#pragma unroll
        for (int l = 0; l < 4; l++) {
            int qc = 4 * tx + l;
            int cc = qc >> 1;
            bool ccopy = ((qc & 1) == OFF);
            if (rcopy) {
                res[l] = ccopy ? s_in[(rr + 6) * SPAN + cc + 6]
                               : s_hi[(rr + 6) * HIW + cc];
            } else {
                float acc = 0.f;
                if (ccopy) {
#pragma unroll
                    for (int v = 0; v < 12; v++)
                        acc += w[v] * s_in[(rr + v + SH) * SPAN + cc + 6];
                } else {
#pragma unroll
                    for (int v = 0; v < 12; v++)
                        acc += w[v] * s_hi[(rr + v + SH) * HIW + cc];
                }
                res[l] = acc;
            }
        }
        float4 o = make_float4(res[0], res[1], res[2], res[3]);
        *reinterpret_cast<float4*>(
            &outc[(size_t)(2 * R0 + qr) * W2 + (size_t)(2 * C0 + 4 * tx)]) = o;
    }
}

extern "C" void kernel_launch(void* const* d_in, const int* in_sizes, int n_in,
                              void* d_out, int out_size)
{
    const float* x    = (const float*)d_in[0];   // (4,8,256,256) fp32
    const float* kern = (const float*)d_in[1];   // 23 taps fp32
    float* out = (float*)d_out;                  // (4,8,1024,1024) fp32

    float* mid = nullptr;
    cudaGetSymbolAddress((void**)&mid, g_mid);   // host query, no alloc, capture-safe

    dim3 blk(16, 16);
    // Round 0: off=1, 256 -> 512
    up2x_kernel<1><<<dim3(256 / TT, 256 / TT, 32), blk>>>(x,   kern, mid, 256);
    // Round 1: off=0, 512 -> 1024
    up2x_kernel<0><<<dim3(512 / TT, 512 / TT, 32), blk>>>(mid, kern, out, 512);
}

// round 2
// speedup vs baseline: 1.2426x; 1.2426x over previous
#include <cuda_runtime.h>

// 2x upsample stage: zero-stuff (offset OFF) + separable circular 23-tap conv,
// as halfband polyphase: parity==OFF outputs are copies, the other parity is a
// 12-tap interpolation with weights kernel[0,2,...,22].
// Stage 1: 256 -> 512 (OFF=1), Stage 2: 512 -> 1024 (OFF=0).

#define TT   32          // tile edge in input domain
#define INW  44          // TT + 12 halo (local j <-> global base-6+j)
#define SPAN 48          // padded smem stride (16B-aligned rows)
#define HIW  32          // smem stride for H-interp tile

// Intermediate 32 channels x 512 x 512 fp32 (33.5 MB) — static device scratch.
__device__ float g_mid[32u * 512u * 512u];

template<int OFF>
__global__ __launch_bounds__(256) void up2x_kernel(
    const float* __restrict__ in, const float* __restrict__ kern,
    float* __restrict__ out, int N)
{
    __shared__ __align__(16) float s_in[INW * SPAN];  // input tile + halo
    __shared__ __align__(16) float s_hi[INW * HIW];   // H-interp, all 44 rows x 32 cols
    __shared__ float s_w[12];

    const int ch = blockIdx.z;
    const int R0 = blockIdx.y * TT;
    const int C0 = blockIdx.x * TT;
    const float* inc  = in  + (size_t)ch * N * N;
    float*       outc = out + (size_t)ch * 4u * (size_t)N * N;

    const int tid = threadIdx.x;
    if (tid < 12) s_w[tid] = kern[2 * tid];   // halfband: nonzero taps at even idx

    // ---- phase 1: load 44x44 input tile (circular wrap) ----
    for (int idx = tid; idx < INW * INW; idx += 256) {
        int i = idx / INW, j = idx - i * INW;
        int gr = R0 - 6 + i; if (gr < 0) gr += N; else if (gr >= N) gr -= N;
        int gc = C0 - 6 + j; if (gc < 0) gc += N; else if (gc >= N) gc -= N;
        s_in[i * SPAN + j] = inc[(size_t)gr * N + gc];
    }
    __syncthreads();

    float w[12];
#pragma unroll
    for (int u = 0; u < 12; u++) w[u] = s_w[u];

    constexpr int SH = OFF ? 0 : 1;  // window start: local m+SH .. m+SH+11

    // ---- phase 2: H-interp hi[i][m], all 44 rows. 4 outputs/unit from regs ----
    for (int idx = tid; idx < INW * 8; idx += 256) {
        int i = idx >> 3, g = idx & 7;          // row, col-group (4 cols)
        float v[20];
        const float4* p = reinterpret_cast<const float4*>(&s_in[i * SPAN + 4 * g]);
#pragma unroll
        for (int q = 0; q < 5; q++) {
            float4 t = p[q];
            v[4 * q + 0] = t.x; v[4 * q + 1] = t.y;
            v[4 * q + 2] = t.z; v[4 * q + 3] = t.w;
        }
        float h[4];
#pragma unroll
        for (int m = 0; m < 4; m++) {
            float acc = 0.f;
#pragma unroll
            for (int u = 0; u < 12; u++) acc += w[u] * v[m + SH + u];
            h[m] = acc;
        }
        *reinterpret_cast<float4*>(&s_hi[i * HIW + 4 * g]) =
            make_float4(h[0], h[1], h[2], h[3]);
    }
    __syncthreads();

    // ---- phase 3: emission. thread = (column c, row-group rg of 4 rows) ----
    const int c  = tid & 31;
    const int rg = tid >> 5;
    const int rb = rg * 4 + SH;                 // vertical window base row (local)

    float a[15], b[15];
#pragma unroll
    for (int n = 0; n < 15; n++) {
        a[n] = s_in[(rb + n) * SPAN + c + 6];
        b[n] = s_hi[(rb + n) * HIW + c];
    }

    const size_t W2 = 2 * (size_t)N;
    const size_t oc = 2 * (size_t)(C0 + c);
#pragma unroll
    for (int k = 0; k < 4; k++) {
        float cc = a[k + 6 - SH];               // copy row, copy col
        float ch = b[k + 6 - SH];               // copy row, interp col
        float vc = 0.f, vh = 0.f;
#pragma unroll
        for (int v = 0; v < 12; v++) {
            vc += w[v] * a[k + v];              // interp row, copy col
            vh += w[v] * b[k + v];              // interp row, interp col
        }
        int r = rg * 4 + k;
        size_t row_copy = (size_t)(2 * (R0 + r) + OFF)       * W2 + oc;
        size_t row_int  = (size_t)(2 * (R0 + r) + (1 - OFF)) * W2 + oc;
        // even col is interp when OFF==1, copy when OFF==0
        float2 rc = OFF ? make_float2(ch, cc) : make_float2(cc, ch);
        float2 ri = OFF ? make_float2(vh, vc) : make_float2(vc, vh);
        *reinterpret_cast<float2*>(&outc[row_copy]) = rc;
        *reinterpret_cast<float2*>(&outc[row_int])  = ri;
    }
}

extern "C" void kernel_launch(void* const* d_in, const int* in_sizes, int n_in,
                              void* d_out, int out_size)
{
    const float* x    = (const float*)d_in[0];   // (4,8,256,256) fp32
    const float* kern = (const float*)d_in[1];   // 23 taps fp32
    float* out = (float*)d_out;                  // (4,8,1024,1024) fp32

    float* mid = nullptr;
    cudaGetSymbolAddress((void**)&mid, g_mid);

    up2x_kernel<1><<<dim3(256 / TT, 256 / TT, 32), 256>>>(x,   kern, mid, 256);
    up2x_kernel<0><<<dim3(512 / TT, 512 / TT, 32), 256>>>(mid, kern, out, 512);
}

// round 3
// speedup vs baseline: 1.9281x; 1.5517x over previous
#include <cuda_runtime.h>

// 2x upsample stage: zero-stuff (offset OFF) + separable circular 23-tap conv,
// as halfband polyphase: parity==OFF outputs are copies, the other parity is a
// 12-tap interpolation with weights kernel[0,2,...,22].
// Stage 1: 256 -> 512 (OFF=1), Stage 2: 512 -> 1024 (OFF=0).

#define TT   32          // tile edge in input domain
#define INW  44          // TT + 12 halo (local j <-> global base-6+j)
#define SPAN 48          // padded smem stride (16B-aligned rows)
#define HIW  32          // smem stride for H-interp tile

// Intermediate 32 channels x 512 x 512 fp32 (33.5 MB) — static device scratch.
__device__ float g_mid[32u * 512u * 512u];

template<int OFF, int N>
__global__ __launch_bounds__(256) void up2x_kernel(
    const float* __restrict__ in, const float* __restrict__ kern,
    float* __restrict__ out)
{
    constexpr int SH = OFF ? 0 : 1;   // interp window shift
    constexpr int W2 = 2 * N;

    __shared__ __align__(16) float s_in[INW * SPAN];
    __shared__ __align__(16) float s_hi[INW * HIW];
    __shared__ float s_w[12];

    const int ch = blockIdx.z;
    const int R0 = blockIdx.y * TT;
    const int C0 = blockIdx.x * TT;
    const float* inc  = in  + ch * (N * N);
    float*       outc = out + ch * (4 * N * N);

    const int tid = threadIdx.x;
    if (tid < 12) s_w[tid] = kern[2 * tid];   // halfband: nonzero taps

    // ---- phase 1: load 44x44 input tile, circular wrap via mask ----
#pragma unroll
    for (int t = 0; t < 8; t++) {
        int idx = tid + t * 256;
        if (idx < INW * INW) {
            int i = idx / INW, j = idx - i * INW;
            int gr = (R0 - 6 + i) & (N - 1);
            int gc = (C0 - 6 + j) & (N - 1);
            s_in[i * SPAN + j] = inc[gr * N + gc];
        }
    }
    __syncthreads();

    float w[12];
#pragma unroll
    for (int u = 0; u < 12; u++) w[u] = s_w[u];

    // ---- phase 2: H-interp, streamed. unit = (row i, 4-col group g) ----
#pragma unroll
    for (int t = 0; t < 2; t++) {
        int idx = tid + t * 256;               // INW*8 = 352 units
        if (idx < INW * 8) {
            int i = idx >> 3, g = idx & 7;
            const float4* p = reinterpret_cast<const float4*>(&s_in[i * SPAN + 4 * g]);
            float h[4] = {0.f, 0.f, 0.f, 0.f};
#pragma unroll
            for (int q = 0; q < 5; q++) {
                float4 tq = p[q];
                float vv[4] = {tq.x, tq.y, tq.z, tq.w};
#pragma unroll
                for (int e = 0; e < 4; e++) {
                    int n = 4 * q + e;
#pragma unroll
                    for (int m = 0; m < 4; m++) {
                        int u = n - SH - m;
                        if (u >= 0 && u < 12) h[m] += w[u] * vv[e];
                    }
                }
            }
            *reinterpret_cast<float4*>(&s_hi[i * HIW + 4 * g]) =
                make_float4(h[0], h[1], h[2], h[3]);
        }
    }
    __syncthreads();

    // ---- phase 3: emission, streamed. thread = (column c, row-group rg) ----
    const int c  = tid & 31;
    const int rg = tid >> 5;
    const float* pa = &s_in[(rg * 4 + SH) * SPAN + c + 6];
    const float* pb = &s_hi[(rg * 4 + SH) * HIW + c];
    float* ob = outc + (2 * (R0 + rg * 4)) * W2 + 2 * (C0 + c);

    float vc[4] = {0.f, 0.f, 0.f, 0.f};
    float vh[4] = {0.f, 0.f, 0.f, 0.f};
#pragma unroll
    for (int n = 0; n < 15; n++) {
        float av = pa[n * SPAN];
        float bv = pb[n * HIW];
#pragma unroll
        for (int k = 0; k < 4; k++) {
            int u = n - k;
            if (u >= 0 && u < 12) { vc[k] += w[u] * av; vh[k] += w[u] * bv; }
        }
#pragma unroll
        for (int k = 0; k < 4; k++) {
            if (n == k + 6 - SH) {             // copy row for output row-pair k
                float2 rc = OFF ? make_float2(bv, av) : make_float2(av, bv);
                *reinterpret_cast<float2*>(&ob[(2 * k + OFF) * W2]) = rc;
            }
        }
    }
#pragma unroll
    for (int k = 0; k < 4; k++) {
        float2 ri = OFF ? make_float2(vh[k], vc[k]) : make_float2(vc[k], vh[k]);
        *reinterpret_cast<float2*>(&ob[(2 * k + 1 - OFF) * W2]) = ri;
    }
}

extern "C" void kernel_launch(void* const* d_in, const int* in_sizes, int n_in,
                              void* d_out, int out_size)
{
    const float* x    = (const float*)d_in[0];   // (4,8,256,256) fp32
    const float* kern = (const float*)d_in[1];   // 23 taps fp32
    float* out = (float*)d_out;                  // (4,8,1024,1024) fp32

    float* mid = nullptr;
    cudaGetSymbolAddress((void**)&mid, g_mid);

    up2x_kernel<1, 256><<<dim3(8, 8, 32),   256>>>(x,   kern, mid);
    up2x_kernel<0, 512><<<dim3(16, 16, 32), 256>>>(mid, kern, out);
}

// round 4
// speedup vs baseline: 2.3946x; 1.2420x over previous
#include <cuda_runtime.h>

// Fully fused 4x upsampler: two halfband-polyphase 2x stages in one kernel.
// Stage 1 (OFF=1): x(256^2) -> mid(512^2), copies at odd positions,
//   interp at even position 2c over x cols c-6..c+5 (12 taps w[u]=kernel[2u]).
// Stage 2 (OFF=0): mid -> out(1024^2), copies at even positions,
//   interp at odd position 2c+1 over mid cols c-5..c+6.
// Each block emits a 128x128 output tile; mid lives only in shared memory.

__global__ __launch_bounds__(256) void fused_up4x(
    const float* __restrict__ in, const float* __restrict__ kern,
    float* __restrict__ out)
{
    constexpr int XS = 56, H1S = 40, MS = 80, H2S = 64;

    __shared__ __align__(16) float s_mid[76 * MS];   // mid tile rows t=0..75 (75 used)
    __shared__ __align__(16) float s_B[4864];        // region B: {s_x,s_h1} then s_h2
    __shared__ float s_w[12];
    float* const s_x  = s_B;                 // 48 x XS   (2688 floats)
    float* const s_h1 = s_B + 48 * XS;       // 48 x H1S  (1920 floats)
    float* const s_h2 = s_B;                 // 75 x H2S  (4800 floats), aliases x/h1

    const int ch = blockIdx.z;
    const int by = blockIdx.y, bx = blockIdx.x;
    const int X0 = 32 * by, XC0 = 32 * bx;   // x-domain tile bases
    const float* inc  = in  + ch * 65536;
    float*       outc = out + ch * 1048576;
    const int tid = threadIdx.x;
    if (tid < 12) s_w[tid] = kern[2 * tid];

    // ---- P1: load 48x48 x tile (rows/cols base-8, circular wrap) ----
#pragma unroll
    for (int t = 0; t < 9; t++) {
        int idx = tid + 256 * t;
        if (idx < 48 * 48) {
            int i = idx / 48, j = idx - i * 48;
            int gr = (X0 - 8 + i) & 255;
            int gc = (XC0 - 8 + j) & 255;
            s_x[i * XS + j] = inc[gr * 256 + gc];
        }
    }
    __syncthreads();

    float w[12];
#pragma unroll
    for (int u = 0; u < 12; u++) w[u] = s_w[u];

    // ---- P2: h1[li][hs] = sum_u w[u]*s_x[li][hs+u]; hs in [0,40), groups of 4 ----
#pragma unroll
    for (int t = 0; t < 2; t++) {
        int idx = tid + 256 * t;
        if (idx < 48 * 10) {
            int li = idx / 10, g = idx - li * 10;
            const float4* p = reinterpret_cast<const float4*>(&s_x[li * XS + 4 * g]);
            float v[16];
#pragma unroll
            for (int q = 0; q < 4; q++) {
                float4 tq = p[q];
                v[4*q] = tq.x; v[4*q+1] = tq.y; v[4*q+2] = tq.z; v[4*q+3] = tq.w;
            }
            float h[4] = {0.f, 0.f, 0.f, 0.f};
#pragma unroll
            for (int n = 0; n < 16; n++)
#pragma unroll
                for (int e = 0; e < 4; e++) {
                    int u = n - e;
                    if (u >= 0 && u < 12) h[e] += w[u] * v[n];
                }
            *reinterpret_cast<float4*>(&s_h1[li * H1S + 4 * g]) =
                make_float4(h[0], h[1], h[2], h[3]);
        }
    }
    __syncthreads();

    // ---- P3: assemble mid tile. thread = (mid col s, rowgroup g of 38 rows) ----
    // mid local row t <-> global M0-5+t (M0=64*by). t even: copy of src row k+5
    // (k = t/2 within group). t odd: 12-tap interp over src rows 19g+k..+11.
    // col s even -> src = s_x col 5+s/2 ; s odd -> src = s_h1 col (s-1)/2.
    {
        bool run = false; int g = 0, s = 0, stride = 0;
        const float* srcc = nullptr;
        if (tid < 128) {                       // even cols: 38 cols x 2 groups
            int u = tid;
            if (u < 76) { int e = u % 38; g = u / 38; s = 2 * e;
                          srcc = &s_x[5 + e]; stride = XS; run = true; }
        } else {                               // odd cols: 37 cols x 2 groups
            int u = tid - 128;
            if (u < 74) { int o = u % 37; g = u / 37; s = 2 * o + 1;
                          srcc = &s_h1[o]; stride = H1S; run = true; }
        }
        if (run) {
            float acc[19];
#pragma unroll
            for (int k = 0; k < 19; k++) acc[k] = 0.f;
#pragma unroll
            for (int n = 0; n < 30; n++) {
                int srow = 19 * g + n;
                if (srow < 48) {
                    float v = srcc[srow * stride];
#pragma unroll
                    for (int k = 0; k < 19; k++) {
                        int u = n - k;
                        if (u >= 0 && u < 12) acc[k] += w[u] * v;
                        if (n == k + 5) s_mid[(38 * g + 2 * k) * MS + s] = v;
                    }
                }
            }
#pragma unroll
            for (int k = 0; k < 19; k++) {
                int t = 38 * g + 2 * k + 1;
                if (t < 75) s_mid[t * MS + s] = acc[k];
            }
        }
    }
    __syncthreads();

    // ---- P4: h2[t][j] = sum_u w[u]*s_mid[t][j+u]; t<75, j<64, groups of 8 ----
#pragma unroll
    for (int it = 0; it < 3; it++) {
        int idx = tid + 256 * it;
        if (idx < 75 * 8) {
            int t = idx / 8, g8 = idx - t * 8;
            const float4* p = reinterpret_cast<const float4*>(&s_mid[t * MS + 8 * g8]);
            float v[20];
#pragma unroll
            for (int q = 0; q < 5; q++) {
                float4 tq = p[q];
                v[4*q] = tq.x; v[4*q+1] = tq.y; v[4*q+2] = tq.z; v[4*q+3] = tq.w;
            }
            float h[8];
#pragma unroll
            for (int e = 0; e < 8; e++) h[e] = 0.f;
#pragma unroll
            for (int n = 0; n < 19; n++)
#pragma unroll
                for (int e = 0; e < 8; e++) {
                    int u = n - e;
                    if (u >= 0 && u < 12) h[e] += w[u] * v[n];
                }
            float4* q4 = reinterpret_cast<float4*>(&s_h2[t * H2S + 8 * g8]);
            q4[0] = make_float4(h[0], h[1], h[2], h[3]);
            q4[1] = make_float4(h[4], h[5], h[6], h[7]);
        }
    }
    __syncthreads();

    // ---- P5: emission. thread = (col pair p in [0,64), rowgroup g of 32 rows) ----
    {
        const int p = tid & 63, g = tid >> 6;
        const float* pa = &s_mid[(16 * g) * MS + p + 5];   // copy-col source
        const float* pb = &s_h2[(16 * g) * H2S + p];       // interp-col source
        float* ob = outc + (128 * by + 32 * g) * 1024 + 128 * bx + 2 * p;

        float vc[16], vh[16];
#pragma unroll
        for (int k = 0; k < 16; k++) { vc[k] = 0.f; vh[k] = 0.f; }
#pragma unroll
        for (int n = 0; n < 27; n++) {
            float a = pa[n * MS];
            float b = pb[n * H2S];
#pragma unroll
            for (int k = 0; k < 16; k++) {
                int u = n - k;
                if (u >= 0 && u < 12) { vc[k] += w[u] * a; vh[k] += w[u] * b; }
                if (n == k + 5)       // copy row (even f): even col=mid, odd col=h2
                    *reinterpret_cast<float2*>(&ob[(2 * k) * 1024]) = make_float2(a, b);
            }
        }
#pragma unroll
        for (int k = 0; k < 16; k++)
            *reinterpret_cast<float2*>(&ob[(2 * k + 1) * 1024]) =
                make_float2(vc[k], vh[k]);
    }
}

extern "C" void kernel_launch(void* const* d_in, const int* in_sizes, int n_in,
                              void* d_out, int out_size)
{
    const float* x    = (const float*)d_in[0];   // (4,8,256,256) fp32
    const float* kern = (const float*)d_in[1];   // 23 taps fp32
    float* out = (float*)d_out;                  // (4,8,1024,1024) fp32

    fused_up4x<<<dim3(8, 8, 32), 256>>>(x, kern, out);
}

// round 5
// speedup vs baseline: 2.8671x; 1.1973x over previous
#include <cuda_runtime.h>

// Fully fused 4x upsampler, two halfband-polyphase 2x stages, no mid tensor.
// Stage 1 (OFF=1): mid[2i+1,2j+1]=x[i,j]; mid even = 12-tap interp (w[u]=kern[2u]).
// Stage 2 (OFF=0): out even = mid copy; out odd 2c+1 = 12-tap over mid c-5..c+6.
// Per block: 128x128 output tile. smem holds x tile, h1 (stage-1 H-interp rows),
// and q (stage-2 H-interp of each interleaved source row). Vertical work for both
// stages is composed on the fly in registers during emission.

#define XS 57   // x row stride (odd -> conflict-free column access)
#define HS 41   // h1 row stride
#define QS 65   // q row stride

__global__ __launch_bounds__(256) void fused_up4x(
    const float* __restrict__ in, const float* __restrict__ kern,
    float* __restrict__ out)
{
    __shared__ float s_x [48 * XS];   // x rows: local i <-> global 32*by-8+i
    __shared__ float s_h1[48 * HS];   // h1[i][hs]: mid even col 2*(32bx+hs-2)
    __shared__ float s_q [48 * QS];   // q[i][j] = stage-2 H-interp of src row i
    __shared__ float s_w [12];

    const int ch = blockIdx.z, by = blockIdx.y, bx = blockIdx.x;
    const float* inc  = in  + ch * 65536;
    float*       outc = out + ch * 1048576;
    const int tid = threadIdx.x;
    if (tid < 12) s_w[tid] = kern[2 * tid];

    // ---- P1: load 48x48 x tile (base -8, circular wrap mod 256) ----
#pragma unroll
    for (int t = 0; t < 9; t++) {
        int idx = tid + 256 * t;
        if (idx < 2304) {
            int i = idx / 48, j = idx - i * 48;
            int gr = (32 * by - 8 + i) & 255;
            int gc = (32 * bx - 8 + j) & 255;
            s_x[i * XS + j] = inc[gr * 256 + gc];
        }
    }
    __syncthreads();

    float w[12];
#pragma unroll
    for (int u = 0; u < 12; u++) w[u] = s_w[u];

    // ---- P2: fused h1 + q. unit = (row i, chunk g in [0,4)) ----
    // h1[i][8g+d] (d<13) and q[i][16g+m] (m<16) from x[i][8g..8g+23].
    if (tid < 192) {
        const int i = tid % 48, g = tid / 48;
        const float* xr = &s_x[i * XS + 8 * g];
        float X[24];
#pragma unroll
        for (int e = 0; e < 24; e++) X[e] = xr[e];

        float H[13];
#pragma unroll
        for (int d = 0; d < 13; d++) {
            float acc = 0.f;
#pragma unroll
            for (int u = 0; u < 12; u++) acc += w[u] * X[d + u];
            H[d] = acc;
        }
        float* hr = &s_h1[i * HS + 8 * g];
#pragma unroll
        for (int d = 0; d < 13; d++) hr[d] = H[d];

        // q[jq]: 6 x-taps + 6 h1-taps (parity split of the interleaved window)
        float* qr = &s_q[i * QS + 16 * g];
#pragma unroll
        for (int m = 0; m < 16; m++) {
            float acc = 0.f;
            if (m & 1) {
#pragma unroll
                for (int e = 0; e < 6; e++)
                    acc += w[2*e+1] * X[(m+1)/2 + 5 + e] + w[2*e] * H[(m-1)/2 + e];
            } else {
#pragma unroll
                for (int e = 0; e < 6; e++)
                    acc += w[2*e] * X[m/2 + 5 + e] + w[2*e+1] * H[m/2 + e];
            }
            qr[m] = acc;
        }
    }
    __syncthreads();

    // ---- P3: emission. thread = (col pair p in [0,64), row group g in [0,4)) ----
    // Streams mid local rows n=0..26 (t = 16g+n): even n -> copy of src row
    // (offset n/2+5), odd n -> 12-tap V-interp of src offsets (n-1)/2..+11.
    // mid copy-col source: p odd -> x col (p+5)/2+5 ; p even -> h1 col (p+4)/2.
    // h2 col p streams identically from q col p.
    {
        const int p = tid & 63, g = tid >> 6;
        const float* pa; int sa;
        if (p & 1) { pa = &s_x [(8 * g) * XS + ((p + 5) >> 1) + 5]; sa = XS; }
        else       { pa = &s_h1[(8 * g) * HS + ((p + 4) >> 1)];     sa = HS; }
        const float* pq = &s_q[(8 * g) * QS + p];

        float A[12], Q[12];                 // rotating windows, offset o -> [o%12]
#pragma unroll
        for (int o = 0; o < 12; o++) { A[o] = pa[o * sa]; Q[o] = pq[o * QS]; }

        float vc[16], vh[16];
#pragma unroll
        for (int k = 0; k < 16; k++) { vc[k] = 0.f; vh[k] = 0.f; }

        float* ob = outc + (128 * by + 32 * g) * 1024 + 128 * bx + 2 * p;

#pragma unroll
        for (int n = 0; n < 27; n++) {
            float mA, mQ;
            if (n & 1) {
                if (n >= 3) {
                    const int onew = (n - 1) / 2 + 11;
                    A[onew % 12] = pa[onew * sa];
                    Q[onew % 12] = pq[onew * QS];
                }
                const int k0 = (n - 1) >> 1;
                float a = 0.f, q = 0.f;
#pragma unroll
                for (int u = 0; u < 12; u++) {
                    a += w[u] * A[(k0 + u) % 12];
                    q += w[u] * Q[(k0 + u) % 12];
                }
                mA = a; mQ = q;
            } else {
                mA = A[(n / 2 + 5) % 12];
                mQ = Q[(n / 2 + 5) % 12];
            }
            // stage-2 vertical interp accumulators (odd output rows)
#pragma unroll
            for (int k = 0; k < 16; k++) {
                const int u = n - k;
                if (u >= 0 && u < 12) { vc[k] += w[u] * mA; vh[k] += w[u] * mQ; }
            }
            // stage-2 vertical copy (even output rows): mid row t = 16g+k+5
            if (n >= 5 && n < 21)
                *reinterpret_cast<float2*>(&ob[(2 * (n - 5)) * 1024]) =
                    make_float2(mA, mQ);
        }
#pragma unroll
        for (int k = 0; k < 16; k++)
            *reinterpret_cast<float2*>(&ob[(2 * k + 1) * 1024]) =
                make_float2(vc[k], vh[k]);
    }
}

extern "C" void kernel_launch(void* const* d_in, const int* in_sizes, int n_in,
                              void* d_out, int out_size)
{
    const float* x    = (const float*)d_in[0];   // (4,8,256,256) fp32
    const float* kern = (const float*)d_in[1];   // 23 taps fp32
    float* out = (float*)d_out;                  // (4,8,1024,1024) fp32

    fused_up4x<<<dim3(8, 8, 32), 256>>>(x, kern, out);
}

// round 6
// speedup vs baseline: 3.2597x; 1.1370x over previous
#include <cuda_runtime.h>

// Fully fused 4x upsampler, two halfband-polyphase 2x stages, no mid tensor.
// Stage 1 (OFF=1): mid[2i+1,2j+1]=x[i,j]; mid even = 12-tap interp (w[u]=kern[2u]).
// Stage 2 (OFF=0): out even = mid copy; out odd 2c+1 = 12-tap over mid c-5..c+6.
// Per block: 128x128 output tile. P2 builds s_c[i][p] = (copy-col value, q value)
// packed as 64 bits; emission runs entirely on packed f32x2 FMA (FFMA2).

typedef unsigned long long ull;

#define FMA2(d, a, b, c) \
    asm("fma.rn.f32x2 %0, %1, %2, %3;" : "=l"(d) : "l"(a), "l"(b), "l"(c))
#define PK2(d, lo, hi) \
    asm("mov.b64 %0, {%1, %2};" : "=l"(d) : "f"(lo), "f"(hi))

#define XS  52   // x row stride in floats (i*52 mod 32-banks: conflict-free LDS.128)
#define CS  65   // s_c row stride in 8-byte elems (odd -> conflict-free LDS.64)
#define W2(u) w2[(u) < 6 ? (u) : 11 - (u)]   // halfband taps are symmetric

__global__ __launch_bounds__(256) void fused_up4x(
    const float* __restrict__ in, const float* __restrict__ kern,
    float* __restrict__ out)
{
    __shared__ __align__(16) float s_x[48 * XS]; // x rows: local i <-> 32*by-8+i
    __shared__ ull  s_c[48 * CS];                // (copy-col, q) packed per out col-pair
    __shared__ float s_w[12];

    const int ch = blockIdx.z, by = blockIdx.y, bx = blockIdx.x;
    const float* inc  = in  + ch * 65536;
    float*       outc = out + ch * 1048576;
    const int tid = threadIdx.x;
    if (tid < 12) s_w[tid] = kern[2 * tid];

    // ---- P1: load 48x48 x tile (base -8, circular wrap mod 256) ----
#pragma unroll
    for (int t = 0; t < 9; t++) {
        int idx = tid + 256 * t;
        if (idx < 2304) {
            int i = idx / 48, j = idx - i * 48;
            int gr = (32 * by - 8 + i) & 255;
            int gc = (32 * bx - 8 + j) & 255;
            s_x[i * XS + j] = inc[gr * 256 + gc];
        }
    }
    __syncthreads();

    float w[12];
#pragma unroll
    for (int u = 0; u < 12; u++) w[u] = s_w[u];
    ull w2[6];
#pragma unroll
    for (int u = 0; u < 6; u++) PK2(w2[u], w[u], w[u]);

    // ---- P2: per (row i, chunk g): H[13] + q[16] + copy vals -> packed s_c ----
    if (tid < 192) {
        const int i = tid % 48, g = tid / 48;
        float X[24];
        const float4* xp = reinterpret_cast<const float4*>(&s_x[i * XS + 8 * g]);
#pragma unroll
        for (int q = 0; q < 6; q++) {
            float4 t = xp[q];
            X[4*q] = t.x; X[4*q+1] = t.y; X[4*q+2] = t.z; X[4*q+3] = t.w;
        }
        float H[13];
#pragma unroll
        for (int d = 0; d < 13; d++) {
            float acc = 0.f;
#pragma unroll
            for (int u = 0; u < 12; u++) acc += w[u] * X[d + u];
            H[d] = acc;
        }
        // s_c[i][16g+m] = (copy value, q value) for output col-pair p=16g+m
#pragma unroll
        for (int m = 0; m < 16; m++) {
            float qv = 0.f;
            if (m & 1) {
#pragma unroll
                for (int e = 0; e < 6; e++)
                    qv += w[2*e+1] * X[(m+1)/2 + 5 + e] + w[2*e] * H[(m-1)/2 + e];
            } else {
#pragma unroll
                for (int e = 0; e < 6; e++)
                    qv += w[2*e] * X[m/2 + 5 + e] + w[2*e+1] * H[m/2 + e];
            }
            float cv = (m & 1) ? X[(m + 15) / 2] : H[m / 2 + 2];
            ull pv; PK2(pv, cv, qv);
            s_c[i * CS + 16 * g + m] = pv;
        }
    }
    __syncthreads();

    // ---- P3: emission, all packed. thread = (col pair p in [0,64), group g) ----
    // Streams mid local rows n=0..26 (t = 16g+n): even n -> copy of src offset
    // n/2+5, odd n -> 12-tap V-interp of src offsets (n-1)/2..+11. Both output
    // columns of the pair ride in one f32x2 lane pair.
    {
        const int p = tid & 63, g = tid >> 6;
        const ull* pc = &s_c[(8 * g) * CS + p];
        float* ob = outc + (128 * by + 32 * g) * 1024 + 128 * bx + 2 * p;

        ull W[12];                           // rotating window, offset o -> [o%12]
#pragma unroll
        for (int o = 0; o < 12; o++) W[o] = pc[o * CS];

        ull acc[16];
#pragma unroll
        for (int k = 0; k < 16; k++) acc[k] = 0ull;

#pragma unroll
        for (int n = 0; n < 27; n++) {
            ull m2;
            if (n & 1) {
                if (n >= 3) {
                    const int onew = (n - 1) / 2 + 11;
                    W[onew % 12] = pc[onew * CS];
                }
                const int k0 = (n - 1) >> 1;
                ull a = 0ull;
#pragma unroll
                for (int u = 0; u < 12; u++)
                    FMA2(a, W2(u), W[(k0 + u) % 12], a);
                m2 = a;
            } else {
                m2 = W[(n / 2 + 5) % 12];
            }
#pragma unroll
            for (int k = 0; k < 16; k++) {
                const int u = n - k;
                if (u >= 0 && u < 12) FMA2(acc[k], W2(u), m2, acc[k]);
            }
            if (n >= 5 && n < 21)            // even output rows: direct copy
                *reinterpret_cast<ull*>(&ob[(2 * (n - 5)) * 1024]) = m2;
        }
#pragma unroll
        for (int k = 0; k < 16; k++)         // odd output rows: V-interp
            *reinterpret_cast<ull*>(&ob[(2 * k + 1) * 1024]) = acc[k];
    }
}

extern "C" void kernel_launch(void* const* d_in, const int* in_sizes, int n_in,
                              void* d_out, int out_size)
{
    const float* x    = (const float*)d_in[0];   // (4,8,256,256) fp32
    const float* kern = (const float*)d_in[1];   // 23 taps fp32
    float* out = (float*)d_out;                  // (4,8,1024,1024) fp32

    fused_up4x<<<dim3(8, 8, 32), 256>>>(x, kern, out);
}